// round 10
// baseline (speedup 1.0000x reference)
#include <cuda_runtime.h>
#include <cuda_bf16.h>
#include <math.h>

// Problem constants (fixed shapes for RoIPointPool3d_23845658427905)
#define BB   4
#define NPTS 16384
#define MM   128
#define CF   128
#define SS   512
#define OUTF (3 + CF)   // 131 floats per pooled row

// ---------------------------------------------------------------------------
// Fused kernel: one CTA per box (512 CTAs, 512 threads).
// Phase 1 (mask): warp w tests points [1024w, 1024w+1024) in 32 chunks of 32.
//   Chunk loads are 3 aligned 128B segments (f0,f1,f2); per-thread (x,y,z)
//   reconstructed with shuffles (bit-identical values). Ballots to smem.
// Phase 2 (compact): one barrier; replay ballots with exclusive warp prefix
//   into smem sidx[] (ordered first-come in-box indices, first SS only).
// Phase 3 (gather): R9 phase-specialized float4 body, indices from smem.
// No global scratch, one launch, mask of one CTA overlaps gather of others.
// ---------------------------------------------------------------------------
__global__ __launch_bounds__(512) void roipool_fused_kernel(
    const float* __restrict__ points,   // (B, N, 3)
    const float* __restrict__ feats,    // (B, N, C)
    const float* __restrict__ boxes,    // (B, M, 7)
    float* __restrict__ out,            // (B, M, S, 131)
    float* __restrict__ flags)          // (B, M)
{
    const int bm = blockIdx.x;          // box id
    const int b  = bm >> 7;             // / MM
    const int tid  = threadIdx.x;
    const int lane = tid & 31;
    const int w    = tid >> 5;          // 0..15

    __shared__ float    sp[8];          // cx, cy, czc, hx, hy, hz, ca, sa
    __shared__ unsigned sball[16][32];
    __shared__ int      wtot[16];
    __shared__ int      sidx[SS];

    // ---- box prep (fp64 sincos, fast-math immune; proven path) ----
    if (tid == 0) {
        const float* bx = boxes + (size_t)bm * 7;
        const float r0 = bx[0], r1 = bx[1], r2 = bx[2];
        const float r3 = bx[3], r4 = bx[4], r5 = bx[5], r6 = bx[6];
        double sv, cv;
        sincos(-(double)r6, &sv, &cv);
        sp[0] = r0;
        sp[1] = r1;
        sp[2] = __fadd_rn(r2, __fmul_rn(0.5f, r5));
        sp[3] = __fmul_rn(0.5f, r3);
        sp[4] = __fmul_rn(0.5f, r4);
        sp[5] = __fmul_rn(0.5f, r5);
        sp[6] = (float)cv;
        sp[7] = (float)sv;
    }
    __syncthreads();

    const float cx = sp[0], cy = sp[1], cz = sp[2];
    const float hx = sp[3], hy = sp[4], hz = sp[5];
    const float ca = sp[6], sa = sp[7];

    // ---- phase 1: membership ballots, warp-local, no block barriers ----
    const unsigned FULL = 0xffffffffu;
    const float* pb = points + ((size_t)b * NPTS + (size_t)w * 1024) * 3;

    // per-thread source mapping for segment reconstruction
    const int i0 = 3 * lane,     s0g = i0 >> 5, o0 = i0 & 31;
    const int i1 = 3 * lane + 1, s1g = i1 >> 5, o1 = i1 & 31;
    const int i2 = 3 * lane + 2, s2g = i2 >> 5, o2 = i2 & 31;

    int cnt = 0;
    for (int j = 0; j < 32; j++) {
        const float f0 = pb[96 * j + lane];
        const float f1 = pb[96 * j + 32 + lane];
        const float f2 = pb[96 * j + 64 + lane];

        // x = float (3*lane), y = (3*lane+1), z = (3*lane+2) of this chunk
        float c0, c1, c2;
        c0 = __shfl_sync(FULL, f0, o0); c1 = __shfl_sync(FULL, f1, o0); c2 = __shfl_sync(FULL, f2, o0);
        const float x = (s0g == 0) ? c0 : ((s0g == 1) ? c1 : c2);
        c0 = __shfl_sync(FULL, f0, o1); c1 = __shfl_sync(FULL, f1, o1); c2 = __shfl_sync(FULL, f2, o1);
        const float y = (s1g == 0) ? c0 : ((s1g == 1) ? c1 : c2);
        c0 = __shfl_sync(FULL, f0, o2); c1 = __shfl_sync(FULL, f1, o2); c2 = __shfl_sync(FULL, f2, o2);
        const float z = (s2g == 0) ? c0 : ((s2g == 1) ? c1 : c2);

        // exact membership test (bit-identical to the proven path)
        const float sx = __fsub_rn(x, cx);
        const float sy = __fsub_rn(y, cy);
        const float lx = __fsub_rn(__fmul_rn(sx, ca), __fmul_rn(sy, sa));
        const float ly = __fadd_rn(__fmul_rn(sx, sa), __fmul_rn(sy, ca));
        const float zd = __fsub_rn(z, cz);
        const bool m = (fabsf(zd) <= hz) && (fabsf(lx) < hx) && (fabsf(ly) < hy);

        const unsigned ball = __ballot_sync(FULL, m);
        if (lane == 0) sball[w][j] = ball;
        cnt += __popc(ball);
    }
    if (lane == 0) wtot[w] = cnt;
    __syncthreads();

    // ---- phase 2: exclusive warp prefix + ballot replay into smem sidx ----
    int run = 0;
    #pragma unroll
    for (int v = 0; v < 16; v++)
        if (v < w) run += wtot[v];
    int tot = 0;
    #pragma unroll
    for (int v = 0; v < 16; v++) tot += wtot[v];

    const unsigned lt = (1u << lane) - 1u;
    #pragma unroll
    for (int j = 0; j < 32; j++) {
        const unsigned ball = sball[w][j];
        const int pre = __popc(ball & lt);
        if (((ball >> lane) & 1u) && (run + pre) < SS)
            sidx[run + pre] = w * 1024 + j * 32 + lane;
        run += __popc(ball);
    }
    if (tid == 0) flags[bm] = (tot == 0) ? 1.0f : 0.0f;
    __syncthreads();

    float* obox = out + (size_t)bm * SS * OUTF;

    if (tot == 0) {
        const float4 zz = make_float4(0.f, 0.f, 0.f, 0.f);
        float4* o4 = (float4*)obox;
        for (int i = tid; i < SS * OUTF / 4; i += 512) o4[i] = zz;
        return;
    }

    // ---- phase 3: gather (R9 phase-specialized float4 body) ----
    const float* pbat = points + (size_t)b * NPTS * 3;
    const float* fbat = feats  + (size_t)b * NPTS * CF;

    const int sw = w * 32;
    for (int i = 0; i < 8; i++) {
        const int sb = sw + i * 4;

        float4 a[4];
        float  pvv[4];
        #pragma unroll
        for (int r = 0; r < 4; r++) {
            const int idx = sidx[(sb + r) % tot];
            a[r]   = ((const float4*)(fbat + (size_t)idx * CF))[lane];
            pvv[r] = (lane < 3) ? pbat[(size_t)idx * 3 + lane] : 0.0f;
        }

        #pragma unroll
        for (int r = 0; r < 4; r++) {
            const float p0 = __shfl_sync(FULL, pvv[r], 0);
            const float p1 = __shfl_sync(FULL, pvv[r], 1);
            const float p2 = __shfl_sync(FULL, pvv[r], 2);

            float4 bq;
            if (r == 3) {
                bq = a[r];
            } else {
                const float ny = __shfl_up_sync(FULL, a[r].y, 1);
                const float nz = __shfl_up_sync(FULL, a[r].z, 1);
                const float nw = __shfl_up_sync(FULL, a[r].w, 1);
                if (r == 0) bq = make_float4(ny, nz, nw, a[r].x);
                if (r == 1) bq = make_float4(nz, nw, a[r].x, a[r].y);
                if (r == 2) bq = make_float4(nw, a[r].x, a[r].y, a[r].z);
            }
            if (lane == 0) {
                if (r == 0) { bq.x = p0; bq.y = p1; bq.z = p2; }
                if (r == 1) { bq.x = p1; bq.y = p2; }
                if (r == 2) { bq.x = p2; }
            }

            float* orow = obox + (size_t)(sb + r) * OUTF;

            // head scalars: cols 0..r-1 are points
            if (lane < r) orow[lane] = (lane == 0) ? p0 : ((lane == 1) ? p1 : p2);

            // main: 32 aligned float4 stores (offset r + 4*lane; (131s+r)%4==0)
            *(float4*)(orow + r + 4 * lane) = bq;

            // tail scalars: cols r+128..130 = feats[r+125..127] from lane 31
            if (r < 3) {
                const float ty = __shfl_sync(FULL, a[r].y, 31);  // feats[125]
                const float tz = __shfl_sync(FULL, a[r].z, 31);  // feats[126]
                const float tw = __shfl_sync(FULL, a[r].w, 31);  // feats[127]
                if (r == 0) { if (lane < 3) orow[128 + lane] = (lane == 0) ? ty : ((lane == 1) ? tz : tw); }
                if (r == 1) { if (lane < 2) orow[129 + lane] = (lane == 0) ? tz : tw; }
                if (r == 2) { if (lane < 1) orow[130] = tw; }
            }
        }
    }
}

// ---------------------------------------------------------------------------
extern "C" void kernel_launch(void* const* d_in, const int* in_sizes, int n_in,
                              void* d_out, int out_size)
{
    const float* points = (const float*)d_in[0];   // (B, N, 3)
    const float* feats  = (const float*)d_in[1];   // (B, N, C)
    const float* boxes  = (const float*)d_in[2];   // (B, M, 7)

    float* out   = (float*)d_out;
    float* flags = out + (size_t)BB * MM * SS * OUTF;  // empty flags appended

    roipool_fused_kernel<<<BB * MM, 512>>>(points, feats, boxes, out, flags);
}

// round 11
// speedup vs baseline: 1.7746x; 1.7746x over previous
#include <cuda_runtime.h>
#include <cuda_bf16.h>
#include <math.h>

// Problem constants (fixed shapes for RoIPointPool3d_23845658427905)
#define BB   4
#define NPTS 16384
#define MM   128
#define CF   128
#define SS   512
#define OUTF (3 + CF)   // 131 floats per pooled row
#define BPC  4          // boxes per mask CTA
#define PSPL 4          // point-range splits per box group
#define PPS  (NPTS / PSPL)   // 4096 points per split

// Scratch (device globals — no allocation allowed)
__device__ int g_table[BB * MM * PSPL * SS]; // per (box, split): ordered in-box indices
__device__ int g_cnt[BB * MM * PSPL];        // per (box, split): in-box counts

// ---------------------------------------------------------------------------
// Kernel 1: fused box-prep (fp64 sincos, fast-math immune) + membership +
// ordered compaction. (Proven R5/R8 version — unchanged.)
// ---------------------------------------------------------------------------
__global__ __launch_bounds__(512) void roipool_mask_kernel(
    const float* __restrict__ points,   // (B, N, 3)
    const float* __restrict__ boxes)    // (B, M, 7)
{
    const int split = blockIdx.x & (PSPL - 1);
    const int quad  = blockIdx.x >> 2;       // 0..127
    const int bm0   = quad * BPC;            // first box of the quad
    const int b     = bm0 >> 7;              // / MM

    __shared__ float    sprep[BPC * 8];      // cx, cy, czc, hx, hy, hz, ca, sa
    __shared__ unsigned sball[BPC][16][8];
    __shared__ int      wtot[BPC][16];

    const int tid  = threadIdx.x;
    const int lane = tid & 31;
    const int w    = tid >> 5;

    if (w == 0 && lane < BPC) {
        const int q = lane;
        const float* bx = boxes + (size_t)(bm0 + q) * 7;
        const float r0 = bx[0], r1 = bx[1], r2 = bx[2];
        const float r3 = bx[3], r4 = bx[4], r5 = bx[5], r6 = bx[6];
        double sv, cv;
        sincos(-(double)r6, &sv, &cv);
        float* o = sprep + q * 8;
        o[0] = r0;
        o[1] = r1;
        o[2] = __fadd_rn(r2, __fmul_rn(0.5f, r5));
        o[3] = __fmul_rn(0.5f, r3);
        o[4] = __fmul_rn(0.5f, r4);
        o[5] = __fmul_rn(0.5f, r5);
        o[6] = (float)cv;
        o[7] = (float)sv;
    }
    __syncthreads();

    float cx[BPC], cy[BPC], cz[BPC], hx[BPC], hy[BPC], hz[BPC], ca[BPC], sa[BPC];
    #pragma unroll
    for (int q = 0; q < BPC; q++) {
        cx[q] = sprep[q * 8 + 0]; cy[q] = sprep[q * 8 + 1];
        cz[q] = sprep[q * 8 + 2]; hx[q] = sprep[q * 8 + 3];
        hy[q] = sprep[q * 8 + 4]; hz[q] = sprep[q * 8 + 5];
        ca[q] = sprep[q * 8 + 6]; sa[q] = sprep[q * 8 + 7];
    }

    const int base_local = split * PPS + w * 256;          // batch-relative
    const float* pb = points + ((size_t)b * NPTS + base_local) * 3;

    int cnt[BPC];
    #pragma unroll
    for (int q = 0; q < BPC; q++) cnt[q] = 0;

    for (int j = 0; j < 8; j++) {
        const int i3 = (j * 32 + lane) * 3;
        const float x = pb[i3 + 0];
        const float y = pb[i3 + 1];
        const float z = pb[i3 + 2];
        #pragma unroll
        for (int q = 0; q < BPC; q++) {
            const float sx = __fsub_rn(x, cx[q]);
            const float sy = __fsub_rn(y, cy[q]);
            const float lx = __fsub_rn(__fmul_rn(sx, ca[q]), __fmul_rn(sy, sa[q]));
            const float ly = __fadd_rn(__fmul_rn(sx, sa[q]), __fmul_rn(sy, ca[q]));
            const float zd = __fsub_rn(z, cz[q]);
            const bool m = (fabsf(zd) <= hz[q]) && (fabsf(lx) < hx[q]) && (fabsf(ly) < hy[q]);
            const unsigned ball = __ballot_sync(0xffffffffu, m);
            if (lane == 0) sball[q][w][j] = ball;
            cnt[q] += __popc(ball);
        }
    }
    if (lane == 0) {
        #pragma unroll
        for (int q = 0; q < BPC; q++) wtot[q][w] = cnt[q];
    }
    __syncthreads();

    const unsigned lt = (1u << lane) - 1u;
    #pragma unroll
    for (int q = 0; q < BPC; q++) {
        int run = 0;
        #pragma unroll
        for (int v = 0; v < 16; v++)
            if (v < w) run += wtot[q][v];
        int* tbl = g_table + (size_t)((bm0 + q) * PSPL + split) * SS;
        #pragma unroll
        for (int j = 0; j < 8; j++) {
            const unsigned ball = sball[q][w][j];
            const int pre = __popc(ball & lt);
            if (((ball >> lane) & 1u) && (run + pre) < SS)
                tbl[run + pre] = base_local + j * 32 + lane;
            run += __popc(ball);
        }
    }

    if (tid < BPC) {
        int tot = 0;
        #pragma unroll
        for (int v = 0; v < 16; v++) tot += wtot[tid][v];
        g_cnt[(bm0 + tid) * PSPL + split] = tot;
    }
}

// ---------------------------------------------------------------------------
// Kernel 2: gather — the best-measured R2 body (one CTA per box, 512 threads,
// 16 warps, 2 rows per iteration, plain scalar loads/stores) with the proven
// 4-split pf[] wrap-around resolution.
// ---------------------------------------------------------------------------
__global__ __launch_bounds__(512) void roipool_gather_kernel(
    const float* __restrict__ points,   // (B, N, 3)
    const float* __restrict__ feats,    // (B, N, C)
    float* __restrict__ out,            // (B, M, S, 131)
    float* __restrict__ flags)          // (B, M)
{
    const int bm = blockIdx.x;
    const int b  = bm >> 7;             // / MM
    const int tid  = threadIdx.x;
    const int lane = tid & 31;
    const int w    = tid >> 5;

    __shared__ int sidx[SS];
    __shared__ int pf[4];
    __shared__ int scnt;

    if (tid == 0) {
        const int c0 = g_cnt[bm * PSPL + 0];
        const int c1 = g_cnt[bm * PSPL + 1];
        const int c2 = g_cnt[bm * PSPL + 2];
        const int c3 = g_cnt[bm * PSPL + 3];
        pf[0] = 0; pf[1] = c0; pf[2] = c0 + c1; pf[3] = c0 + c1 + c2;
        const int tot = c0 + c1 + c2 + c3;
        scnt = tot;
        flags[bm] = (tot == 0) ? 1.0f : 0.0f;
    }
    __syncthreads();
    const int cnt = scnt;

    float* obox = out + (size_t)bm * SS * OUTF;

    if (cnt == 0) {
        const float4 zz = make_float4(0.f, 0.f, 0.f, 0.f);
        float4* o4 = (float4*)obox;
        for (int i = tid; i < SS * OUTF / 4; i += 512) o4[i] = zz;
        return;
    }

    // resolve wrap-around index for this thread's row across the 4 splits
    {
        const int s = tid;                       // SS == blockDim.x
        const int j = s % cnt;
        const int p = (j >= pf[3]) ? 3 : (j >= pf[2]) ? 2 : (j >= pf[1]) ? 1 : 0;
        sidx[s] = g_table[(size_t)(bm * PSPL + p) * SS + (j - pf[p])];
    }
    __syncthreads();

    const float* pbat = points + (size_t)b * NPTS * 3;
    const float* fbat = feats  + (size_t)b * NPTS * CF;

    // each warp: rows s = w, w+16, ..., two rows per iteration (R2 body)
    for (int s = w; s < SS; s += 32) {
        const int s2  = s + 16;
        const int ia  = sidx[s];
        const int ib  = sidx[s2];
        const float* fa = fbat + (size_t)ia * CF;
        const float* fb = fbat + (size_t)ib * CF;
        const float* pa = pbat + (size_t)ia * 3;
        const float* pb = pbat + (size_t)ib * 3;
        float* oa = obox + (size_t)s  * OUTF;
        float* ob = obox + (size_t)s2 * OUTF;

        // row A loads (e = lane + 32k), coalesced
        const float a0 = (lane < 3) ? pa[lane] : fa[lane - 3];
        const float a1 = fa[lane + 29];
        const float a2 = fa[lane + 61];
        const float a3 = fa[lane + 93];
        float a4 = 0.f; if (lane < 3) a4 = fa[lane + 125];
        // row B loads
        const float b0 = (lane < 3) ? pb[lane] : fb[lane - 3];
        const float b1 = fb[lane + 29];
        const float b2 = fb[lane + 61];
        const float b3 = fb[lane + 93];
        float b4 = 0.f; if (lane < 3) b4 = fb[lane + 125];

        oa[lane]       = a0;
        oa[lane + 32]  = a1;
        oa[lane + 64]  = a2;
        oa[lane + 96]  = a3;
        if (lane < 3) oa[lane + 128] = a4;
        ob[lane]       = b0;
        ob[lane + 32]  = b1;
        ob[lane + 64]  = b2;
        ob[lane + 96]  = b3;
        if (lane < 3) ob[lane + 128] = b4;
    }
}

// ---------------------------------------------------------------------------
extern "C" void kernel_launch(void* const* d_in, const int* in_sizes, int n_in,
                              void* d_out, int out_size)
{
    const float* points = (const float*)d_in[0];   // (B, N, 3)
    const float* feats  = (const float*)d_in[1];   // (B, N, C)
    const float* boxes  = (const float*)d_in[2];   // (B, M, 7)

    float* out   = (float*)d_out;
    float* flags = out + (size_t)BB * MM * SS * OUTF;  // empty flags appended

    roipool_mask_kernel<<<(BB * MM / BPC) * PSPL, 512>>>(points, boxes);
    roipool_gather_kernel<<<BB * MM, 512>>>(points, feats, out, flags);
}

// round 12
// speedup vs baseline: 1.9355x; 1.0907x over previous
#include <cuda_runtime.h>
#include <cuda_bf16.h>
#include <math.h>

// Problem constants (fixed shapes for RoIPointPool3d_23845658427905)
#define BB   4
#define NPTS 16384
#define MM   128
#define CF   128
#define SS   512
#define OUTF (3 + CF)   // 131 floats per pooled row
#define BPC  4          // boxes per mask CTA
#define PSPL 4          // point-range splits per box group
#define PPS  (NPTS / PSPL)   // 4096 points per split
#define NMASK ((BB * MM / BPC) * PSPL)   // 512 mask CTAs

// Scratch (device globals — no allocation allowed; zero-initialized at load)
__device__ int g_table[BB * MM * PSPL * SS]; // per (box, split): ordered in-box indices
__device__ int g_cnt[BB * MM * PSPL];        // per (box, split): in-box counts
__device__ int g_done[BB * MM];              // per box: completed-split count (self-resetting)

// ---------------------------------------------------------------------------
// Single-launch producer/consumer pipeline.
// bid < 512 : mask CTA (proven R5/R8 body) for quad bid>>2, split bid&3.
//             Publishes tables, then fence + atomicAdd(g_done[box]) x4.
// bid >= 512: gather CTA (proven R2 body) for box bid-512. Spins until its
//             box's 4 splits arrive, consumes, resets the counter (so every
//             graph replay starts from the same state), then gathers.
// Dispatcher feeds CTAs in bid order -> all producers schedule before
// consumers -> no deadlock; early gathers overlap late masks.
// ---------------------------------------------------------------------------
__global__ __launch_bounds__(512) void roipool_pipe_kernel(
    const float* __restrict__ points,   // (B, N, 3)
    const float* __restrict__ feats,    // (B, N, C)
    const float* __restrict__ boxes,    // (B, M, 7)
    float* __restrict__ out,            // (B, M, S, 131)
    float* __restrict__ flags)          // (B, M)
{
    const int tid  = threadIdx.x;
    const int lane = tid & 31;
    const int w    = tid >> 5;

    if (blockIdx.x < NMASK) {
        // =================== MASK (producer) ===================
        const int split = blockIdx.x & (PSPL - 1);
        const int quad  = blockIdx.x >> 2;       // 0..127
        const int bm0   = quad * BPC;            // first box of the quad
        const int b     = bm0 >> 7;              // / MM

        __shared__ float    sprep[BPC * 8];      // cx, cy, czc, hx, hy, hz, ca, sa
        __shared__ unsigned sball[BPC][16][8];
        __shared__ int      wtot[BPC][16];

        if (w == 0 && lane < BPC) {
            const int q = lane;
            const float* bx = boxes + (size_t)(bm0 + q) * 7;
            const float r0 = bx[0], r1 = bx[1], r2 = bx[2];
            const float r3 = bx[3], r4 = bx[4], r5 = bx[5], r6 = bx[6];
            double sv, cv;
            sincos(-(double)r6, &sv, &cv);
            float* o = sprep + q * 8;
            o[0] = r0;
            o[1] = r1;
            o[2] = __fadd_rn(r2, __fmul_rn(0.5f, r5));
            o[3] = __fmul_rn(0.5f, r3);
            o[4] = __fmul_rn(0.5f, r4);
            o[5] = __fmul_rn(0.5f, r5);
            o[6] = (float)cv;
            o[7] = (float)sv;
        }
        __syncthreads();

        float cx[BPC], cy[BPC], cz[BPC], hx[BPC], hy[BPC], hz[BPC], ca[BPC], sa[BPC];
        #pragma unroll
        for (int q = 0; q < BPC; q++) {
            cx[q] = sprep[q * 8 + 0]; cy[q] = sprep[q * 8 + 1];
            cz[q] = sprep[q * 8 + 2]; hx[q] = sprep[q * 8 + 3];
            hy[q] = sprep[q * 8 + 4]; hz[q] = sprep[q * 8 + 5];
            ca[q] = sprep[q * 8 + 6]; sa[q] = sprep[q * 8 + 7];
        }

        const int base_local = split * PPS + w * 256;          // batch-relative
        const float* pb = points + ((size_t)b * NPTS + base_local) * 3;

        int cnt[BPC];
        #pragma unroll
        for (int q = 0; q < BPC; q++) cnt[q] = 0;

        for (int j = 0; j < 8; j++) {
            const int i3 = (j * 32 + lane) * 3;
            const float x = pb[i3 + 0];
            const float y = pb[i3 + 1];
            const float z = pb[i3 + 2];
            #pragma unroll
            for (int q = 0; q < BPC; q++) {
                const float sx = __fsub_rn(x, cx[q]);
                const float sy = __fsub_rn(y, cy[q]);
                const float lx = __fsub_rn(__fmul_rn(sx, ca[q]), __fmul_rn(sy, sa[q]));
                const float ly = __fadd_rn(__fmul_rn(sx, sa[q]), __fmul_rn(sy, ca[q]));
                const float zd = __fsub_rn(z, cz[q]);
                const bool m = (fabsf(zd) <= hz[q]) && (fabsf(lx) < hx[q]) && (fabsf(ly) < hy[q]);
                const unsigned ball = __ballot_sync(0xffffffffu, m);
                if (lane == 0) sball[q][w][j] = ball;
                cnt[q] += __popc(ball);
            }
        }
        if (lane == 0) {
            #pragma unroll
            for (int q = 0; q < BPC; q++) wtot[q][w] = cnt[q];
        }
        __syncthreads();

        const unsigned lt = (1u << lane) - 1u;
        #pragma unroll
        for (int q = 0; q < BPC; q++) {
            int run = 0;
            #pragma unroll
            for (int v = 0; v < 16; v++)
                if (v < w) run += wtot[q][v];
            int* tbl = g_table + (size_t)((bm0 + q) * PSPL + split) * SS;
            #pragma unroll
            for (int j = 0; j < 8; j++) {
                const unsigned ball = sball[q][w][j];
                const int pre = __popc(ball & lt);
                if (((ball >> lane) & 1u) && (run + pre) < SS)
                    tbl[run + pre] = base_local + j * 32 + lane;
                run += __popc(ball);
            }
        }

        if (tid < BPC) {
            int tot = 0;
            #pragma unroll
            for (int v = 0; v < 16; v++) tot += wtot[tid][v];
            g_cnt[(bm0 + tid) * PSPL + split] = tot;
        }

        // publish: make table/cnt visible at gpu scope, then arrive
        __threadfence();
        __syncthreads();
        if (tid < BPC) atomicAdd(&g_done[bm0 + tid], 1);

    } else {
        // =================== GATHER (consumer) ===================
        const int bm = blockIdx.x - NMASK;   // box id
        const int b  = bm >> 7;              // / MM

        __shared__ int sidx[SS];
        __shared__ int pf[4];
        __shared__ int scnt;

        // wait for this box's 4 split producers
        if (tid == 0) {
            volatile int* vd = g_done;
            while (vd[bm] < PSPL) __nanosleep(64);
            __threadfence();   // acquire: order subsequent reads after the flag
        }
        __syncthreads();

        if (tid == 0) {
            const int c0 = g_cnt[bm * PSPL + 0];
            const int c1 = g_cnt[bm * PSPL + 1];
            const int c2 = g_cnt[bm * PSPL + 2];
            const int c3 = g_cnt[bm * PSPL + 3];
            pf[0] = 0; pf[1] = c0; pf[2] = c0 + c1; pf[3] = c0 + c1 + c2;
            const int tot = c0 + c1 + c2 + c3;
            scnt = tot;
            flags[bm] = (tot == 0) ? 1.0f : 0.0f;
        }
        __syncthreads();
        const int cnt = scnt;

        float* obox = out + (size_t)bm * SS * OUTF;

        if (cnt > 0) {
            const int s = tid;                       // SS == blockDim.x
            const int j = s % cnt;
            const int p = (j >= pf[3]) ? 3 : (j >= pf[2]) ? 2 : (j >= pf[1]) ? 1 : 0;
            sidx[s] = g_table[(size_t)(bm * PSPL + p) * SS + (j - pf[p])];
        }
        __syncthreads();

        // all g_table/g_cnt reads done: reset the flag for the next replay
        if (tid == 0) atomicSub(&g_done[bm], PSPL);

        if (cnt == 0) {
            const float4 zz = make_float4(0.f, 0.f, 0.f, 0.f);
            float4* o4 = (float4*)obox;
            for (int i = tid; i < SS * OUTF / 4; i += 512) o4[i] = zz;
            return;
        }

        const float* pbat = points + (size_t)b * NPTS * 3;
        const float* fbat = feats  + (size_t)b * NPTS * CF;

        // proven R2 gather body: each warp rows s = w, w+16, ...; 2 rows/iter
        for (int s = w; s < SS; s += 32) {
            const int s2  = s + 16;
            const int ia  = sidx[s];
            const int ib  = sidx[s2];
            const float* fa = fbat + (size_t)ia * CF;
            const float* fb = fbat + (size_t)ib * CF;
            const float* pa = pbat + (size_t)ia * 3;
            const float* pb = pbat + (size_t)ib * 3;
            float* oa = obox + (size_t)s  * OUTF;
            float* ob = obox + (size_t)s2 * OUTF;

            const float a0 = (lane < 3) ? pa[lane] : fa[lane - 3];
            const float a1 = fa[lane + 29];
            const float a2 = fa[lane + 61];
            const float a3 = fa[lane + 93];
            float a4 = 0.f; if (lane < 3) a4 = fa[lane + 125];
            const float b0 = (lane < 3) ? pb[lane] : fb[lane - 3];
            const float b1 = fb[lane + 29];
            const float b2 = fb[lane + 61];
            const float b3 = fb[lane + 93];
            float b4 = 0.f; if (lane < 3) b4 = fb[lane + 125];

            oa[lane]       = a0;
            oa[lane + 32]  = a1;
            oa[lane + 64]  = a2;
            oa[lane + 96]  = a3;
            if (lane < 3) oa[lane + 128] = a4;
            ob[lane]       = b0;
            ob[lane + 32]  = b1;
            ob[lane + 64]  = b2;
            ob[lane + 96]  = b3;
            if (lane < 3) ob[lane + 128] = b4;
        }
    }
}

// ---------------------------------------------------------------------------
extern "C" void kernel_launch(void* const* d_in, const int* in_sizes, int n_in,
                              void* d_out, int out_size)
{
    const float* points = (const float*)d_in[0];   // (B, N, 3)
    const float* feats  = (const float*)d_in[1];   // (B, N, C)
    const float* boxes  = (const float*)d_in[2];   // (B, M, 7)

    float* out   = (float*)d_out;
    float* flags = out + (size_t)BB * MM * SS * OUTF;  // empty flags appended

    roipool_pipe_kernel<<<NMASK + BB * MM, 512>>>(points, feats, boxes, out, flags);
}